// round 15
// baseline (speedup 1.0000x reference)
#include <cuda_runtime.h>
#include <cuda_fp16.h>
#include <cstdint>

#define Bn   4
#define Sn   2048
#define Dn   768
#define Hn   12
#define HDn  64
#define MTOT (Bn * Sn)   // 8192
#define XEL  (MTOT * Dn) // 6291456
#define WEL  (Dn * Dn)   // 589824

// Scratch — static device globals (no allocation)
__device__ __half g_q[Bn * Hn * Sn * HDn];     // [B,H,S,d], pre-scaled by log2e/8
__device__ __half g_k[Bn * Hn * Sn * HDn];     // [B,H,S,d]
__device__ __half g_vT[Bn * Hn * HDn * Sn];    // [B,H,d,S]
__device__ __half g_ctx[Bn * Hn * Sn * HDn];   // [B,H,S,d]
__device__ __half g_xh[3][XEL];                // fp16 q/k/v inputs
__device__ __half g_wh[4][WEL];                // fp16 TRANSPOSED weights [n][k]

#define SWZ(off) ((off) ^ (((off) >> 3) & 0x70))

__device__ __forceinline__ void cp16s(unsigned sa, const void* g) {
    asm volatile("cp.async.cg.shared.global [%0], [%1], 16;\n" :: "r"(sa), "l"(g));
}
__device__ __forceinline__ void cp_commit() { asm volatile("cp.async.commit_group;\n"); }
template <int N> __device__ __forceinline__ void cp_wait() {
    asm volatile("cp.async.wait_group %0;\n" :: "n"(N));
}
__device__ __forceinline__ void ldsm4(unsigned* d, unsigned a) {
    asm volatile("ldmatrix.sync.aligned.m8n8.x4.shared.b16 {%0,%1,%2,%3}, [%4];"
                 : "=r"(d[0]), "=r"(d[1]), "=r"(d[2]), "=r"(d[3]) : "r"(a));
}
__device__ __forceinline__ void mma16(float* d, const unsigned* a, unsigned b0, unsigned b1) {
    asm volatile("mma.sync.aligned.m16n8k16.row.col.f32.f16.f16.f32 "
                 "{%0,%1,%2,%3}, {%4,%5,%6,%7}, {%8,%9}, {%0,%1,%2,%3};"
                 : "+f"(d[0]), "+f"(d[1]), "+f"(d[2]), "+f"(d[3])
                 : "r"(a[0]), "r"(a[1]), "r"(a[2]), "r"(a[3]), "r"(b0), "r"(b1));
}
__device__ __forceinline__ float ex2f(float x) {
    float y; asm("ex2.approx.f32 %0, %1;" : "=f"(y) : "f"(x)); return y;
}

// ---------------------------------------------------------------------------
// fp16 conversion of activations (8 elems/thread)
// ---------------------------------------------------------------------------
__global__ void conv_x_kernel(const float* __restrict__ x0, const float* __restrict__ x1,
                              const float* __restrict__ x2) {
    const float* src = (blockIdx.y == 0) ? x0 : (blockIdx.y == 1) ? x1 : x2;
    __half* dst = g_xh[blockIdx.y];
    int i = (blockIdx.x * 256 + threadIdx.x) * 8;
    float4 a = *(const float4*)(src + i);
    float4 b = *(const float4*)(src + i + 4);
    __half2 h[4];
    h[0] = __floats2half2_rn(a.x, a.y);
    h[1] = __floats2half2_rn(a.z, a.w);
    h[2] = __floats2half2_rn(b.x, b.y);
    h[3] = __floats2half2_rn(b.z, b.w);
    *(uint4*)(dst + i) = *(uint4*)h;
}

// ---------------------------------------------------------------------------
// Transpose + fp16 weights: g_wh[z][n][k] = half(W_z[k][n])
// ---------------------------------------------------------------------------
__global__ void transw_kernel(const float* __restrict__ w0, const float* __restrict__ w1,
                              const float* __restrict__ w2, const float* __restrict__ w3) {
    const float* src = (blockIdx.z == 0) ? w0 : (blockIdx.z == 1) ? w1
                     : (blockIdx.z == 2) ? w2 : w3;
    __half* dst = g_wh[blockIdx.z];
    __shared__ float t[32][33];
    int kt = blockIdx.x * 32, nt = blockIdx.y * 32;
#pragma unroll
    for (int p = 0; p < 4; p++) {
        int e = threadIdx.x + 256 * p;
        int r = e >> 5, c = e & 31;
        t[r][c] = src[(size_t)(kt + r) * Dn + nt + c];
    }
    __syncthreads();
#pragma unroll
    for (int p = 0; p < 4; p++) {
        int e = threadIdx.x + 256 * p;
        int r = e >> 5, c = e & 31;
        dst[(size_t)(nt + r) * Dn + kt + c] = __float2half(t[c][r]);
    }
}

// ---------------------------------------------------------------------------
// Merged QKV projection — 3-stage cp.async pipeline, one sync per K-chunk.
// ---------------------------------------------------------------------------
#define GSMEM 99328

__global__ __launch_bounds__(256, 2)
void qkv_kernel(const float* __restrict__ bq, const float* __restrict__ bk,
                const float* __restrict__ bv)
{
    extern __shared__ char smc[];
    unsigned sb = (unsigned)__cvta_generic_to_shared(smc);
    unsigned ab = (sb + 1023u) & ~1023u;
    float* sst = (float*)(smc + (ab - sb));

    const int z = blockIdx.z;
    const __half* A  = g_xh[z];
    const __half* Wt = g_wh[z];
    const float* bias = (z == 0) ? bq : (z == 1) ? bk : bv;

    const int tid = threadIdx.x;
    const int w = tid >> 5, lane = tid & 31;
    const int wm = w & 1, wn = w >> 1;
    const int g = lane >> 2, tg = lane & 3;
    const int m0 = blockIdx.x * 128, n0 = blockIdx.y * 128;
    const int b_ = m0 >> 11, s0 = m0 & 2047;

    float acc[4][4][4];
#pragma unroll
    for (int mi = 0; mi < 4; mi++)
#pragma unroll
        for (int ni = 0; ni < 4; ni++)
#pragma unroll
            for (int e = 0; e < 4; e++) acc[mi][ni][e] = 0.0f;

    auto issue = [&](int c) {
        unsigned buf = (unsigned)(c % 3) * 32768u;
        int k0 = c * 64;
#pragma unroll
        for (int jj = 0; jj < 4; jj++) {
            int i = tid + 256 * jj;
            int r = i >> 3, c8 = i & 7;
            cp16s(ab + buf + SWZ(r * 128 + c8 * 16), A + (size_t)(m0 + r) * Dn + k0 + c8 * 8);
        }
#pragma unroll
        for (int jj = 0; jj < 4; jj++) {
            int i = tid + 256 * jj;
            int r = i >> 3, c8 = i & 7;
            cp16s(ab + buf + 16384u + SWZ(r * 128 + c8 * 16),
                  Wt + (size_t)(n0 + r) * Dn + k0 + c8 * 8);
        }
        cp_commit();
    };

    issue(0);
    issue(1);
    const int arow = lane & 15, ak = (lane >> 4) * 16;

    for (int c = 0; c < 12; c++) {
        if (c < 11) cp_wait<1>(); else cp_wait<0>();
        __syncthreads();
        if (c + 2 < 12) issue(c + 2);
        unsigned abase = ab + (unsigned)(c % 3) * 32768u;
        unsigned bbase = abase + 16384u;
#pragma unroll
        for (int s = 0; s < 4; s++) {
            unsigned ar[4][4], br[2][4];
#pragma unroll
            for (int mi = 0; mi < 4; mi++)
                ldsm4(ar[mi], abase + SWZ((wm * 64 + mi * 16 + arow) * 128 + s * 32 + ak));
#pragma unroll
            for (int nj = 0; nj < 2; nj++)
                ldsm4(br[nj], bbase + SWZ((wn * 32 + nj * 16 + arow) * 128 + s * 32 + ak));
#pragma unroll
            for (int mi = 0; mi < 4; mi++)
#pragma unroll
                for (int ni = 0; ni < 4; ni++)
                    mma16(acc[mi][ni], ar[mi], br[ni >> 1][ni & 1], br[ni >> 1][(ni & 1) + 2]);
        }
    }
    __syncthreads();

#pragma unroll
    for (int mi = 0; mi < 4; mi++)
#pragma unroll
        for (int ni = 0; ni < 4; ni++) {
            int row0 = wm * 64 + mi * 16 + g;
            int col = wn * 32 + ni * 8 + tg * 2;
            *(float2*)(sst + row0 * 132 + col) = make_float2(acc[mi][ni][0], acc[mi][ni][1]);
            *(float2*)(sst + (row0 + 8) * 132 + col) = make_float2(acc[mi][ni][2], acc[mi][ni][3]);
        }
    __syncthreads();

    if (z < 2) {
        __half* outh = (z == 0) ? g_q : g_k;
        float scale = (z == 0) ? (0.125f * 1.44269504f) : 1.0f;
        int col = tid & 127, rh = (tid >> 7) * 64;
        int nn = n0 + col, hh = nn >> 6, dd = nn & 63;
        float bvl = bias[nn];
        __half* op = outh + (((size_t)b_ * Hn + hh) * Sn + s0) * HDn + dd;
        for (int r = rh; r < rh + 64; r++)
            op[(size_t)r * HDn] = __float2half(scale * (sst[r * 132 + col] + bvl));
    } else {
        int r = tid & 127, ch = (tid >> 7) * 64;
        for (int c = ch; c < ch + 64; c++) {
            int nn = n0 + c, hh = nn >> 6, dd = nn & 63;
            g_vT[(((size_t)b_ * Hn + hh) * HDn + dd) * Sn + s0 + r] =
                __float2half(sst[r * 132 + c] + bias[nn]);
        }
    }
}

// ---------------------------------------------------------------------------
// Output projection — same 3-stage, 1-sync pipeline.
// ---------------------------------------------------------------------------
__global__ __launch_bounds__(256, 2)
void outproj_kernel(const float* __restrict__ bias, float* __restrict__ out)
{
    extern __shared__ char smc[];
    unsigned sb = (unsigned)__cvta_generic_to_shared(smc);
    unsigned ab = (sb + 1023u) & ~1023u;
    float* sst = (float*)(smc + (ab - sb));

    const __half* Wt = g_wh[3];
    const int tid = threadIdx.x;
    const int w = tid >> 5, lane = tid & 31;
    const int wm = w & 1, wn = w >> 1;
    const int g = lane >> 2, tg = lane & 3;
    const int m0 = blockIdx.x * 128, n0 = blockIdx.y * 128;
    const int b_ = m0 >> 11, s0 = m0 & 2047;

    float acc[4][4][4];
#pragma unroll
    for (int mi = 0; mi < 4; mi++)
#pragma unroll
        for (int ni = 0; ni < 4; ni++)
#pragma unroll
            for (int e = 0; e < 4; e++) acc[mi][ni][e] = 0.0f;

    auto issue = [&](int c) {
        unsigned buf = (unsigned)(c % 3) * 32768u;
#pragma unroll
        for (int jj = 0; jj < 4; jj++) {
            int i = tid + 256 * jj;
            int r = i >> 3, c8 = i & 7;
            cp16s(ab + buf + SWZ(r * 128 + c8 * 16),
                  g_ctx + (((size_t)b_ * Hn + c) * Sn + s0 + r) * HDn + c8 * 8);
        }
#pragma unroll
        for (int jj = 0; jj < 4; jj++) {
            int i = tid + 256 * jj;
            int r = i >> 3, c8 = i & 7;
            cp16s(ab + buf + 16384u + SWZ(r * 128 + c8 * 16),
                  Wt + (size_t)(n0 + r) * Dn + c * 64 + c8 * 8);
        }
        cp_commit();
    };

    issue(0);
    issue(1);
    const int arow = lane & 15, ak = (lane >> 4) * 16;

    for (int c = 0; c < 12; c++) {
        if (c < 11) cp_wait<1>(); else cp_wait<0>();
        __syncthreads();
        if (c + 2 < 12) issue(c + 2);
        unsigned abase = ab + (unsigned)(c % 3) * 32768u;
        unsigned bbase = abase + 16384u;
#pragma unroll
        for (int s = 0; s < 4; s++) {
            unsigned ar[4][4], br[2][4];
#pragma unroll
            for (int mi = 0; mi < 4; mi++)
                ldsm4(ar[mi], abase + SWZ((wm * 64 + mi * 16 + arow) * 128 + s * 32 + ak));
#pragma unroll
            for (int nj = 0; nj < 2; nj++)
                ldsm4(br[nj], bbase + SWZ((wn * 32 + nj * 16 + arow) * 128 + s * 32 + ak));
#pragma unroll
            for (int mi = 0; mi < 4; mi++)
#pragma unroll
                for (int ni = 0; ni < 4; ni++)
                    mma16(acc[mi][ni], ar[mi], br[ni >> 1][ni & 1], br[ni >> 1][(ni & 1) + 2]);
        }
    }
    __syncthreads();

#pragma unroll
    for (int mi = 0; mi < 4; mi++)
#pragma unroll
        for (int ni = 0; ni < 4; ni++) {
            int row0 = wm * 64 + mi * 16 + g;
            int col = wn * 32 + ni * 8 + tg * 2;
            *(float2*)(sst + row0 * 132 + col) = make_float2(acc[mi][ni][0], acc[mi][ni][1]);
            *(float2*)(sst + (row0 + 8) * 132 + col) = make_float2(acc[mi][ni][2], acc[mi][ni][3]);
        }
    __syncthreads();

    int col = tid & 127, rh = (tid >> 7) * 64;
    float bvl = bias[n0 + col];
    float* op = out + (size_t)m0 * Dn + n0 + col;
    for (int r = rh; r < rh + 64; r++)
        op[(size_t)r * Dn] = sst[r * 132 + col] + bvl;
}

// ---------------------------------------------------------------------------
// fp16 fused attention — R8 structure + MMA-BASED ROW SUMS (P @ ones-column).
// The ones-block B fragment is k-invariant: loaded ONCE from a 2KB static
// smem region (row0 = 1.0h, rows 1-15 = 0). Per PV chunk: +2 mma into osum.
// Removes all per-tile FADD/SHFL/smem row-sum machinery.
// smem: 1KB pad + QS 16KB | KS 2x16KB | VS 2x8KB | PS 2x16KB | SONE 2KB | lrow 512B
// ---------------------------------------------------------------------------
#define ATTN_SMEM 101888

__global__ __launch_bounds__(256, 2)
void attn_kernel()
{
    extern __shared__ char smc[];
    unsigned sb = (unsigned)__cvta_generic_to_shared(smc);
    unsigned ab = (sb + 1023u) & ~1023u;
    char* abp = smc + (ab - sb);

    const unsigned QS = ab;
    const unsigned KS = ab + 16384u;        // two 16KB buffers
    const unsigned VS = ab + 49152u;        // two 8KB panels (kv halves)
    const unsigned PS = ab + 65536u;        // two 16KB panels (kv halves)
    const unsigned SONE = ab + 98304u;      // 2KB ones-block (16 rows x 128B)
    float* lrow = (float*)(abp + 100352);   // [128]

    const int tid = threadIdx.x;
    const int w = tid >> 5, lane = tid & 31;
    const int wm = w & 3, wn = w >> 2;
    const int g = lane >> 2, tg = lane & 3;
    const int b = blockIdx.z, h = blockIdx.y, q0 = blockIdx.x * 128;

    const __half* Qg  = g_q  + (((size_t)b * Hn + h) * Sn + q0) * HDn;
    const __half* Kg  = g_k  + (((size_t)b * Hn + h) * Sn) * HDn;
    const __half* VTg = g_vT + (((size_t)b * Hn + h) * HDn) * Sn;

    auto issueK = [&](int t) {
        unsigned kb = KS + (unsigned)(t & 1) * 16384u;
#pragma unroll
        for (int jj = 0; jj < 4; jj++) {
            int i = tid + 256 * jj;
            int r = i >> 3, c8 = i & 7;
            cp16s(kb + SWZ(r * 128 + c8 * 16), Kg + (size_t)(t * 128 + r) * HDn + c8 * 8);
        }
        cp_commit();
    };
    auto issueV = [&](int t) {
#pragma unroll
        for (int jj = 0; jj < 4; jj++) {
            int i = tid + 256 * jj;
            int r = i >> 4, c16 = i & 15;
            cp16s(VS + (unsigned)(c16 >> 3) * 8192u + SWZ(r * 128 + (c16 & 7) * 16),
                  VTg + (size_t)r * Sn + t * 128 + c16 * 8);
        }
        cp_commit();
    };

    // Prologue: Q + K0 (group 1), V0 (group 2); fill SONE with plain stores.
#pragma unroll
    for (int jj = 0; jj < 4; jj++) {
        int i = tid + 256 * jj;
        int r = i >> 3, c8 = i & 7;
        cp16s(QS + SWZ(r * 128 + c8 * 16), Qg + (size_t)r * HDn + c8 * 8);
    }
    issueK(0);
    issueV(0);

#pragma unroll
    for (int jj = 0; jj < 2; jj++) {
        int idx = tid + 256 * jj;            // 0..511 words
        int row = idx >> 5, wd = idx & 31;
        int chunk = wd >> 2, ww = wd & 3;
        unsigned val = (row == 0) ? 0x3C003C00u : 0u;
        asm volatile("st.shared.u32 [%0], %1;"
                     :: "r"(SONE + SWZ(row * 128 + chunk * 16) + ww * 4), "r"(val));
    }

    float oacc[2][4][4];
#pragma unroll
    for (int mi = 0; mi < 2; mi++)
#pragma unroll
        for (int ni = 0; ni < 4; ni++)
#pragma unroll
            for (int e = 0; e < 4; e++) oacc[mi][ni][e] = 0.0f;
    float osum[2][4];
#pragma unroll
    for (int mi = 0; mi < 2; mi++)
#pragma unroll
        for (int e = 0; e < 4; e++) osum[mi][e] = 0.0f;

    cp_wait<0>();
    __syncthreads();

    const int arow = lane & 15, ak = (lane >> 4) * 16;

    // Ones-block B fragment (k-invariant): load once.
    unsigned ssfr[4];
    ldsm4(ssfr, SONE + SWZ(arow * 128 + ak));

    for (int kt = 0; kt < 16; kt++) {
        if (kt + 1 < 16) issueK(kt + 1);
        unsigned kb = KS + (unsigned)(kt & 1) * 16384u;

#pragma unroll
        for (int hf = 0; hf < 2; hf++) {
            // ---- S_half = Q @ K^T ----
            float sacc[2][4][4];
#pragma unroll
            for (int mi = 0; mi < 2; mi++)
#pragma unroll
                for (int ni = 0; ni < 4; ni++)
#pragma unroll
                    for (int e = 0; e < 4; e++) sacc[mi][ni][e] = 0.0f;

#pragma unroll
            for (int s = 0; s < 4; s++) {
                unsigned ar[2][4], br[2][4];
#pragma unroll
                for (int mi = 0; mi < 2; mi++)
                    ldsm4(ar[mi], QS + SWZ((wm * 32 + mi * 16 + arow) * 128 + s * 32 + ak));
#pragma unroll
                for (int nj = 0; nj < 2; nj++)
                    ldsm4(br[nj], kb + SWZ((hf * 64 + wn * 32 + nj * 16 + arow) * 128 + s * 32 + ak));
#pragma unroll
                for (int mi = 0; mi < 2; mi++)
#pragma unroll
                    for (int ni = 0; ni < 4; ni++)
                        mma16(sacc[mi][ni], ar[mi], br[ni >> 1][ni & 1], br[ni >> 1][(ni & 1) + 2]);
            }

            // ---- ex2 + store P panel hf (row sums now via MMA in PV) ----
            unsigned pp = PS + (unsigned)hf * 16384u;
#pragma unroll
            for (int mi = 0; mi < 2; mi++)
#pragma unroll
                for (int ni = 0; ni < 4; ni++) {
                    float e0 = ex2f(sacc[mi][ni][0]);
                    float e1 = ex2f(sacc[mi][ni][1]);
                    float e2 = ex2f(sacc[mi][ni][2]);
                    float e3 = ex2f(sacc[mi][ni][3]);
                    int row0 = wm * 32 + mi * 16 + g;
                    unsigned cb = (unsigned)(wn * 64 + ni * 16);
                    __half2 p0 = __floats2half2_rn(e0, e1);
                    __half2 p1 = __floats2half2_rn(e2, e3);
                    unsigned ad0 = pp + SWZ(row0 * 128 + cb) + tg * 4;
                    unsigned ad1 = pp + SWZ((row0 + 8) * 128 + cb) + tg * 4;
                    asm volatile("st.shared.u32 [%0], %1;" :: "r"(ad0), "r"(*(unsigned*)&p0));
                    asm volatile("st.shared.u32 [%0], %1;" :: "r"(ad1), "r"(*(unsigned*)&p1));
                }
        }

        // V(kt) landed? groups retire in order: V(kt) precedes K(kt+1).
        if (kt + 1 < 16) cp_wait<1>(); else cp_wait<0>();
        __syncthreads();          // P + V(kt) visible to all warps

        // ---- O += P @ V ; osum += P @ ones ----
        unsigned vb = VS;
#pragma unroll
        for (int c = 0; c < 8; c++) {
            unsigned pp = PS + (unsigned)(c >> 2) * 16384u;
            unsigned vp = vb + (unsigned)(c >> 2) * 8192u;
            int ko = (c & 3) * 32;
            unsigned ar[2][4], br[2][4];
#pragma unroll
            for (int mi = 0; mi < 2; mi++)
                ldsm4(ar[mi], pp + SWZ((wm * 32 + mi * 16 + arow) * 128 + ko + ak));
#pragma unroll
            for (int nj = 0; nj < 2; nj++)
                ldsm4(br[nj], vp + SWZ((wn * 32 + nj * 16 + arow) * 128 + ko + ak));
#pragma unroll
            for (int mi = 0; mi < 2; mi++) {
#pragma unroll
                for (int ni = 0; ni < 4; ni++)
                    mma16(oacc[mi][ni], ar[mi], br[ni >> 1][ni & 1], br[ni >> 1][(ni & 1) + 2]);
                mma16(osum[mi], ar[mi], ssfr[0], ssfr[2]);   // row sums on tensor pipe
            }
        }

        cp_wait<0>();             // K(kt+1) landed
        __syncthreads();          // PV reads done; K(kt+1) visible

        if (kt + 1 < 16) issueV(kt + 1);
    }

    // ---- epilogue: stage O over dead Q/K area; lrow from osum; normalize ----
    float* sst = (float*)abp;     // [128][68] f32 = 34816 B (< QS+KS0 area)
#pragma unroll
    for (int mi = 0; mi < 2; mi++)
#pragma unroll
        for (int ni = 0; ni < 4; ni++) {
            int row0 = wm * 32 + mi * 16 + g;
            int col = wn * 32 + ni * 8 + tg * 2;
            *(float2*)(sst + row0 * 68 + col) = make_float2(oacc[mi][ni][0], oacc[mi][ni][1]);
            *(float2*)(sst + (row0 + 8) * 68 + col) = make_float2(oacc[mi][ni][2], oacc[mi][ni][3]);
        }
    if (wn == 0 && tg == 0) {
#pragma unroll
        for (int mi = 0; mi < 2; mi++) {
            int row0 = wm * 32 + mi * 16 + g;
            lrow[row0]     = osum[mi][0];   // col n=64 (ones) = full row sum
            lrow[row0 + 8] = osum[mi][2];
        }
    }
    __syncthreads();

    __half* Cg = g_ctx + (((size_t)b * Hn + h) * Sn + q0) * HDn;
    for (int idx = tid; idx < 128 * 32; idx += 256) {
        int r = idx >> 5, c2 = (idx & 31) * 2;
        float inv = 1.0f / lrow[r];
        __half2 hv = __floats2half2_rn(sst[r * 68 + c2] * inv, sst[r * 68 + c2 + 1] * inv);
        *(unsigned*)(Cg + (size_t)r * HDn + c2) = *(unsigned*)&hv;
    }
}

// ---------------------------------------------------------------------------
extern "C" void kernel_launch(void* const* d_in, const int* in_sizes, int n_in,
                              void* d_out, int out_size)
{
    const float* query = (const float*)d_in[0];
    const float* key   = (const float*)d_in[1];
    const float* value = (const float*)d_in[2];
    const float* wq    = (const float*)d_in[3];
    const float* bq    = (const float*)d_in[4];
    const float* wk    = (const float*)d_in[5];
    const float* bk    = (const float*)d_in[6];
    const float* wv    = (const float*)d_in[7];
    const float* bv    = (const float*)d_in[8];
    const float* wo    = (const float*)d_in[9];
    const float* bo    = (const float*)d_in[10];
    float* out = (float*)d_out;

    cudaFuncSetAttribute(qkv_kernel,     cudaFuncAttributeMaxDynamicSharedMemorySize, GSMEM);
    cudaFuncSetAttribute(outproj_kernel, cudaFuncAttributeMaxDynamicSharedMemorySize, GSMEM);
    cudaFuncSetAttribute(attn_kernel,    cudaFuncAttributeMaxDynamicSharedMemorySize, ATTN_SMEM);

    dim3 blk256(256);
    conv_x_kernel<<<dim3(XEL / 2048, 3), blk256>>>(query, key, value);
    transw_kernel<<<dim3(24, 24, 4), blk256>>>(wq, wk, wv, wo);

    qkv_kernel<<<dim3(MTOT / 128, Dn / 128, 3), blk256, GSMEM>>>(bq, bk, bv);

    // #4: attention (profiled window)
    attn_kernel<<<dim3(Sn / 128, Hn, Bn), blk256, ATTN_SMEM>>>();

    outproj_kernel<<<dim3(MTOT / 128, Dn / 128), blk256, GSMEM>>>(bo, out);
}

// round 16
// speedup vs baseline: 1.0759x; 1.0759x over previous
#include <cuda_runtime.h>
#include <cuda_fp16.h>
#include <cstdint>

#define Bn   4
#define Sn   2048
#define Dn   768
#define Hn   12
#define HDn  64
#define MTOT (Bn * Sn)   // 8192
#define XEL  (MTOT * Dn) // 6291456
#define WEL  (Dn * Dn)   // 589824

// Scratch — static device globals (no allocation)
__device__ __half g_q[Bn * Hn * Sn * HDn];     // [B,H,S,d], pre-scaled by log2e/8
__device__ __half g_k[Bn * Hn * Sn * HDn];     // [B,H,S,d]
__device__ __half g_vT[Bn * Hn * HDn * Sn];    // [B,H,d,S]
__device__ __half g_ctx[Bn * Hn * Sn * HDn];   // [B,H,S,d]
__device__ __half g_xh[3][XEL];                // fp16 q/k/v inputs
__device__ __half g_wh[4][WEL];                // fp16 TRANSPOSED weights [n][k]

#define SWZ(off) ((off) ^ (((off) >> 3) & 0x70))

__device__ __forceinline__ void cp16s(unsigned sa, const void* g) {
    asm volatile("cp.async.cg.shared.global [%0], [%1], 16;\n" :: "r"(sa), "l"(g));
}
__device__ __forceinline__ void cp_commit() { asm volatile("cp.async.commit_group;\n"); }
template <int N> __device__ __forceinline__ void cp_wait() {
    asm volatile("cp.async.wait_group %0;\n" :: "n"(N));
}
__device__ __forceinline__ void ldsm4(unsigned* d, unsigned a) {
    asm volatile("ldmatrix.sync.aligned.m8n8.x4.shared.b16 {%0,%1,%2,%3}, [%4];"
                 : "=r"(d[0]), "=r"(d[1]), "=r"(d[2]), "=r"(d[3]) : "r"(a));
}
__device__ __forceinline__ void mma16(float* d, const unsigned* a, unsigned b0, unsigned b1) {
    asm volatile("mma.sync.aligned.m16n8k16.row.col.f32.f16.f16.f32 "
                 "{%0,%1,%2,%3}, {%4,%5,%6,%7}, {%8,%9}, {%0,%1,%2,%3};"
                 : "+f"(d[0]), "+f"(d[1]), "+f"(d[2]), "+f"(d[3])
                 : "r"(a[0]), "r"(a[1]), "r"(a[2]), "r"(a[3]), "r"(b0), "r"(b1));
}
__device__ __forceinline__ float ex2f(float x) {
    float y; asm("ex2.approx.f32 %0, %1;" : "=f"(y) : "f"(x)); return y;
}
__device__ __forceinline__ unsigned packh2(float a, float b) {
    __half2 h = __floats2half2_rn(a, b);
    return *(unsigned*)&h;
}

// ---------------------------------------------------------------------------
// fp16 conversion of activations (8 elems/thread)
// ---------------------------------------------------------------------------
__global__ void conv_x_kernel(const float* __restrict__ x0, const float* __restrict__ x1,
                              const float* __restrict__ x2) {
    const float* src = (blockIdx.y == 0) ? x0 : (blockIdx.y == 1) ? x1 : x2;
    __half* dst = g_xh[blockIdx.y];
    int i = (blockIdx.x * 256 + threadIdx.x) * 8;
    float4 a = *(const float4*)(src + i);
    float4 b = *(const float4*)(src + i + 4);
    __half2 h[4];
    h[0] = __floats2half2_rn(a.x, a.y);
    h[1] = __floats2half2_rn(a.z, a.w);
    h[2] = __floats2half2_rn(b.x, b.y);
    h[3] = __floats2half2_rn(b.z, b.w);
    *(uint4*)(dst + i) = *(uint4*)h;
}

// ---------------------------------------------------------------------------
// Transpose + fp16 weights: g_wh[z][n][k] = half(W_z[k][n])
// ---------------------------------------------------------------------------
__global__ void transw_kernel(const float* __restrict__ w0, const float* __restrict__ w1,
                              const float* __restrict__ w2, const float* __restrict__ w3) {
    const float* src = (blockIdx.z == 0) ? w0 : (blockIdx.z == 1) ? w1
                     : (blockIdx.z == 2) ? w2 : w3;
    __half* dst = g_wh[blockIdx.z];
    __shared__ float t[32][33];
    int kt = blockIdx.x * 32, nt = blockIdx.y * 32;
#pragma unroll
    for (int p = 0; p < 4; p++) {
        int e = threadIdx.x + 256 * p;
        int r = e >> 5, c = e & 31;
        t[r][c] = src[(size_t)(kt + r) * Dn + nt + c];
    }
    __syncthreads();
#pragma unroll
    for (int p = 0; p < 4; p++) {
        int e = threadIdx.x + 256 * p;
        int r = e >> 5, c = e & 31;
        dst[(size_t)(nt + r) * Dn + kt + c] = __float2half(t[c][r]);
    }
}

// ---------------------------------------------------------------------------
// Merged QKV projection — 3-stage cp.async pipeline, one sync per K-chunk.
// ---------------------------------------------------------------------------
#define GSMEM 99328

__global__ __launch_bounds__(256, 2)
void qkv_kernel(const float* __restrict__ bq, const float* __restrict__ bk,
                const float* __restrict__ bv)
{
    extern __shared__ char smc[];
    unsigned sb = (unsigned)__cvta_generic_to_shared(smc);
    unsigned ab = (sb + 1023u) & ~1023u;
    float* sst = (float*)(smc + (ab - sb));

    const int z = blockIdx.z;
    const __half* A  = g_xh[z];
    const __half* Wt = g_wh[z];
    const float* bias = (z == 0) ? bq : (z == 1) ? bk : bv;

    const int tid = threadIdx.x;
    const int w = tid >> 5, lane = tid & 31;
    const int wm = w & 1, wn = w >> 1;
    const int g = lane >> 2, tg = lane & 3;
    const int m0 = blockIdx.x * 128, n0 = blockIdx.y * 128;
    const int b_ = m0 >> 11, s0 = m0 & 2047;

    float acc[4][4][4];
#pragma unroll
    for (int mi = 0; mi < 4; mi++)
#pragma unroll
        for (int ni = 0; ni < 4; ni++)
#pragma unroll
            for (int e = 0; e < 4; e++) acc[mi][ni][e] = 0.0f;

    auto issue = [&](int c) {
        unsigned buf = (unsigned)(c % 3) * 32768u;
        int k0 = c * 64;
#pragma unroll
        for (int jj = 0; jj < 4; jj++) {
            int i = tid + 256 * jj;
            int r = i >> 3, c8 = i & 7;
            cp16s(ab + buf + SWZ(r * 128 + c8 * 16), A + (size_t)(m0 + r) * Dn + k0 + c8 * 8);
        }
#pragma unroll
        for (int jj = 0; jj < 4; jj++) {
            int i = tid + 256 * jj;
            int r = i >> 3, c8 = i & 7;
            cp16s(ab + buf + 16384u + SWZ(r * 128 + c8 * 16),
                  Wt + (size_t)(n0 + r) * Dn + k0 + c8 * 8);
        }
        cp_commit();
    };

    issue(0);
    issue(1);
    const int arow = lane & 15, ak = (lane >> 4) * 16;

    for (int c = 0; c < 12; c++) {
        if (c < 11) cp_wait<1>(); else cp_wait<0>();
        __syncthreads();
        if (c + 2 < 12) issue(c + 2);
        unsigned abase = ab + (unsigned)(c % 3) * 32768u;
        unsigned bbase = abase + 16384u;
#pragma unroll
        for (int s = 0; s < 4; s++) {
            unsigned ar[4][4], br[2][4];
#pragma unroll
            for (int mi = 0; mi < 4; mi++)
                ldsm4(ar[mi], abase + SWZ((wm * 64 + mi * 16 + arow) * 128 + s * 32 + ak));
#pragma unroll
            for (int nj = 0; nj < 2; nj++)
                ldsm4(br[nj], bbase + SWZ((wn * 32 + nj * 16 + arow) * 128 + s * 32 + ak));
#pragma unroll
            for (int mi = 0; mi < 4; mi++)
#pragma unroll
                for (int ni = 0; ni < 4; ni++)
                    mma16(acc[mi][ni], ar[mi], br[ni >> 1][ni & 1], br[ni >> 1][(ni & 1) + 2]);
        }
    }
    __syncthreads();

#pragma unroll
    for (int mi = 0; mi < 4; mi++)
#pragma unroll
        for (int ni = 0; ni < 4; ni++) {
            int row0 = wm * 64 + mi * 16 + g;
            int col = wn * 32 + ni * 8 + tg * 2;
            *(float2*)(sst + row0 * 132 + col) = make_float2(acc[mi][ni][0], acc[mi][ni][1]);
            *(float2*)(sst + (row0 + 8) * 132 + col) = make_float2(acc[mi][ni][2], acc[mi][ni][3]);
        }
    __syncthreads();

    if (z < 2) {
        __half* outh = (z == 0) ? g_q : g_k;
        float scale = (z == 0) ? (0.125f * 1.44269504f) : 1.0f;
        int col = tid & 127, rh = (tid >> 7) * 64;
        int nn = n0 + col, hh = nn >> 6, dd = nn & 63;
        float bvl = bias[nn];
        __half* op = outh + (((size_t)b_ * Hn + hh) * Sn + s0) * HDn + dd;
        for (int r = rh; r < rh + 64; r++)
            op[(size_t)r * HDn] = __float2half(scale * (sst[r * 132 + col] + bvl));
    } else {
        int r = tid & 127, ch = (tid >> 7) * 64;
        for (int c = ch; c < ch + 64; c++) {
            int nn = n0 + c, hh = nn >> 6, dd = nn & 63;
            g_vT[(((size_t)b_ * Hn + hh) * HDn + dd) * Sn + s0 + r] =
                __float2half(sst[r * 132 + c] + bias[nn]);
        }
    }
}

// ---------------------------------------------------------------------------
// Output projection — same 3-stage, 1-sync pipeline.
// ---------------------------------------------------------------------------
__global__ __launch_bounds__(256, 2)
void outproj_kernel(const float* __restrict__ bias, float* __restrict__ out)
{
    extern __shared__ char smc[];
    unsigned sb = (unsigned)__cvta_generic_to_shared(smc);
    unsigned ab = (sb + 1023u) & ~1023u;
    float* sst = (float*)(smc + (ab - sb));

    const __half* Wt = g_wh[3];
    const int tid = threadIdx.x;
    const int w = tid >> 5, lane = tid & 31;
    const int wm = w & 1, wn = w >> 1;
    const int g = lane >> 2, tg = lane & 3;
    const int m0 = blockIdx.x * 128, n0 = blockIdx.y * 128;
    const int b_ = m0 >> 11, s0 = m0 & 2047;

    float acc[4][4][4];
#pragma unroll
    for (int mi = 0; mi < 4; mi++)
#pragma unroll
        for (int ni = 0; ni < 4; ni++)
#pragma unroll
            for (int e = 0; e < 4; e++) acc[mi][ni][e] = 0.0f;

    auto issue = [&](int c) {
        unsigned buf = (unsigned)(c % 3) * 32768u;
#pragma unroll
        for (int jj = 0; jj < 4; jj++) {
            int i = tid + 256 * jj;
            int r = i >> 3, c8 = i & 7;
            cp16s(ab + buf + SWZ(r * 128 + c8 * 16),
                  g_ctx + (((size_t)b_ * Hn + c) * Sn + s0 + r) * HDn + c8 * 8);
        }
#pragma unroll
        for (int jj = 0; jj < 4; jj++) {
            int i = tid + 256 * jj;
            int r = i >> 3, c8 = i & 7;
            cp16s(ab + buf + 16384u + SWZ(r * 128 + c8 * 16),
                  Wt + (size_t)(n0 + r) * Dn + c * 64 + c8 * 8);
        }
        cp_commit();
    };

    issue(0);
    issue(1);
    const int arow = lane & 15, ak = (lane >> 4) * 16;

    for (int c = 0; c < 12; c++) {
        if (c < 11) cp_wait<1>(); else cp_wait<0>();
        __syncthreads();
        if (c + 2 < 12) issue(c + 2);
        unsigned abase = ab + (unsigned)(c % 3) * 32768u;
        unsigned bbase = abase + 16384u;
#pragma unroll
        for (int s = 0; s < 4; s++) {
            unsigned ar[4][4], br[2][4];
#pragma unroll
            for (int mi = 0; mi < 4; mi++)
                ldsm4(ar[mi], abase + SWZ((wm * 64 + mi * 16 + arow) * 128 + s * 32 + ak));
#pragma unroll
            for (int nj = 0; nj < 2; nj++)
                ldsm4(br[nj], bbase + SWZ((wn * 32 + nj * 16 + arow) * 128 + s * 32 + ak));
#pragma unroll
            for (int mi = 0; mi < 4; mi++)
#pragma unroll
                for (int ni = 0; ni < 4; ni++)
                    mma16(acc[mi][ni], ar[mi], br[ni >> 1][ni & 1], br[ni >> 1][(ni & 1) + 2]);
        }
    }
    __syncthreads();

#pragma unroll
    for (int mi = 0; mi < 4; mi++)
#pragma unroll
        for (int ni = 0; ni < 4; ni++) {
            int row0 = wm * 64 + mi * 16 + g;
            int col = wn * 32 + ni * 8 + tg * 2;
            *(float2*)(sst + row0 * 132 + col) = make_float2(acc[mi][ni][0], acc[mi][ni][1]);
            *(float2*)(sst + (row0 + 8) * 132 + col) = make_float2(acc[mi][ni][2], acc[mi][ni][3]);
        }
    __syncthreads();

    int col = tid & 127, rh = (tid >> 7) * 64;
    float bvl = bias[n0 + col];
    float* op = out + (size_t)m0 * Dn + n0 + col;
    for (int r = rh; r < rh + 64; r++)
        op[(size_t)r * Dn] = sst[r * 132 + col] + bvl;
}

// ---------------------------------------------------------------------------
// fp16 fused attention v2 — warp owns 16 q-rows x full 128 kv; P lives in
// registers (pk[16][2] = exact m16n8k16 A-fragment layout), ZERO P smem
// traffic, ONE sync per tile (issue-after-barrier double buffering for both
// K and V). Q fragments persistent. Row sums via ones-MMA.
// smem: 1KB pad + QS 16KB | KS 2x16KB | VS 2x16KB | SONE 2KB | lrow 512B
// ---------------------------------------------------------------------------
#define ATTN_SMEM 85504

__global__ __launch_bounds__(256, 2)
void attn_kernel()
{
    extern __shared__ char smc[];
    unsigned sb = (unsigned)__cvta_generic_to_shared(smc);
    unsigned ab = (sb + 1023u) & ~1023u;
    char* abp = smc + (ab - sb);

    const unsigned QS = ab;
    const unsigned KS = ab + 16384u;        // 2 x 16KB
    const unsigned VS = ab + 49152u;        // 2 x 16KB (each: 2 panels [64][64])
    const unsigned SONE = ab + 81920u;      // 2KB ones-block
    float* lrow = (float*)(abp + 83968);    // [128]

    const int tid = threadIdx.x;
    const int w = tid >> 5, lane = tid & 31;
    const int g = lane >> 2, tg = lane & 3;
    const int b = blockIdx.z, h = blockIdx.y, q0 = blockIdx.x * 128;
    const int wq = w * 16;                  // this warp's 16 q rows

    const __half* Qg  = g_q  + (((size_t)b * Hn + h) * Sn + q0) * HDn;
    const __half* Kg  = g_k  + (((size_t)b * Hn + h) * Sn) * HDn;
    const __half* VTg = g_vT + (((size_t)b * Hn + h) * HDn) * Sn;

    auto issueK = [&](int t) {      // 128 kv x 64 d fp16 into KS[t&1]
        unsigned kb = KS + (unsigned)(t & 1) * 16384u;
#pragma unroll
        for (int jj = 0; jj < 4; jj++) {
            int i = tid + 256 * jj;
            int r = i >> 3, c8 = i & 7;
            cp16s(kb + SWZ(r * 128 + c8 * 16), Kg + (size_t)(t * 128 + r) * HDn + c8 * 8);
        }
        cp_commit();
    };
    auto issueV = [&](int t) {      // 64 d x 128 kv fp16 into VS[t&1] (2 panels)
        unsigned vb = VS + (unsigned)(t & 1) * 16384u;
#pragma unroll
        for (int jj = 0; jj < 4; jj++) {
            int i = tid + 256 * jj;
            int r = i >> 4, c16 = i & 15;
            cp16s(vb + (unsigned)(c16 >> 3) * 8192u + SWZ(r * 128 + (c16 & 7) * 16),
                  VTg + (size_t)r * Sn + t * 128 + c16 * 8);
        }
        cp_commit();
    };

    // Prologue: Q (+K0 committed together), V0; fill SONE.
#pragma unroll
    for (int jj = 0; jj < 4; jj++) {
        int i = tid + 256 * jj;
        int r = i >> 3, c8 = i & 7;
        cp16s(QS + SWZ(r * 128 + c8 * 16), Qg + (size_t)r * HDn + c8 * 8);
    }
    issueK(0);
    issueV(0);

#pragma unroll
    for (int jj = 0; jj < 2; jj++) {
        int idx = tid + 256 * jj;
        int row = idx >> 5, wd = idx & 31;
        int chunk = wd >> 2, ww = wd & 3;
        unsigned val = (row == 0) ? 0x3C003C00u : 0u;
        asm volatile("st.shared.u32 [%0], %1;"
                     :: "r"(SONE + SWZ(row * 128 + chunk * 16) + ww * 4), "r"(val));
    }

    float oacc[8][4];
#pragma unroll
    for (int dn = 0; dn < 8; dn++)
#pragma unroll
        for (int e = 0; e < 4; e++) oacc[dn][e] = 0.0f;
    float osum[4] = {0.f, 0.f, 0.f, 0.f};

    cp_wait<0>();
    __syncthreads();

    const int arow = lane & 15, ak = (lane >> 4) * 16;

    // Ones-block B fragment (invariant)
    unsigned sfr[4];
    ldsm4(sfr, SONE + SWZ(arow * 128 + ak));
    const unsigned so0 = sfr[0], so1 = sfr[2];

    // Persistent Q fragments: 4 ldsm4 = 16 regs, valid all tiles
    unsigned qfr[4][4];
#pragma unroll
    for (int s = 0; s < 4; s++)
        ldsm4(qfr[s], QS + SWZ((wq + arow) * 128 + s * 32 + ak));

    for (int kt = 0; kt < 16; kt++) {
        // buffers for THIS tile landed (groups from previous top); sync; then
        // issue next tile into the other buffer (its readers passed barrier).
        if (kt) { cp_wait<0>(); __syncthreads(); }
        if (kt + 1 < 16) { issueK(kt + 1); issueV(kt + 1); }

        unsigned kb = KS + (unsigned)(kt & 1) * 16384u;
        unsigned vb = VS + (unsigned)(kt & 1) * 16384u;

        // ---- QK^T + exp per n-pair; P -> registers ----
        unsigned pk[16][2];
#pragma unroll
        for (int np = 0; np < 8; np++) {
            float sacc[2][4];
#pragma unroll
            for (int j = 0; j < 2; j++)
#pragma unroll
                for (int e = 0; e < 4; e++) sacc[j][e] = 0.0f;
#pragma unroll
            for (int s = 0; s < 4; s++) {
                unsigned br[4];
                ldsm4(br, kb + SWZ((np * 16 + arow) * 128 + s * 32 + ak));
                mma16(sacc[0], qfr[s], br[0], br[2]);
                mma16(sacc[1], qfr[s], br[1], br[3]);
            }
#pragma unroll
            for (int j = 0; j < 2; j++) {
                float e0 = ex2f(sacc[j][0]);
                float e1 = ex2f(sacc[j][1]);
                float e2 = ex2f(sacc[j][2]);
                float e3 = ex2f(sacc[j][3]);
                pk[np * 2 + j][0] = packh2(e0, e1);
                pk[np * 2 + j][1] = packh2(e2, e3);
            }
        }

        // ---- O += P @ V ; osum += P @ ones (A straight from registers) ----
#pragma unroll
        for (int c = 0; c < 8; c++) {
            unsigned a[4] = { pk[2 * c][0], pk[2 * c][1],
                              pk[2 * c + 1][0], pk[2 * c + 1][1] };
            unsigned vp = vb + (unsigned)(c >> 2) * 8192u;
            int ko = (c & 3) * 32;
#pragma unroll
            for (int dp = 0; dp < 4; dp++) {
                unsigned br[4];
                ldsm4(br, vp + SWZ((dp * 16 + arow) * 128 + ko + ak));
                mma16(oacc[dp * 2],     a, br[0], br[2]);
                mma16(oacc[dp * 2 + 1], a, br[1], br[3]);
            }
            mma16(osum, a, so0, so1);
        }
    }

    // ---- epilogue: lrow from osum; stage O; normalize; write ctx ----
    __syncthreads();                 // all KS/VS reads done before overlay
    if (tg == 0) {
        lrow[wq + g]     = osum[0];  // ones column = full row sum
        lrow[wq + 8 + g] = osum[2];
    }
    float* sst = (float*)abp;        // [128][68] f32 = 34816 B (over QS+KS0)
#pragma unroll
    for (int dn = 0; dn < 8; dn++) {
        int row0 = wq + g;
        int col = dn * 8 + tg * 2;
        *(float2*)(sst + row0 * 68 + col) = make_float2(oacc[dn][0], oacc[dn][1]);
        *(float2*)(sst + (row0 + 8) * 68 + col) = make_float2(oacc[dn][2], oacc[dn][3]);
    }
    __syncthreads();

    __half* Cg = g_ctx + (((size_t)b * Hn + h) * Sn + q0) * HDn;
    for (int idx = tid; idx < 128 * 32; idx += 256) {
        int r = idx >> 5, c2 = (idx & 31) * 2;
        float inv = 1.0f / lrow[r];
        __half2 hv = __floats2half2_rn(sst[r * 68 + c2] * inv, sst[r * 68 + c2 + 1] * inv);
        *(unsigned*)(Cg + (size_t)r * HDn + c2) = *(unsigned*)&hv;
    }
}

// ---------------------------------------------------------------------------
extern "C" void kernel_launch(void* const* d_in, const int* in_sizes, int n_in,
                              void* d_out, int out_size)
{
    const float* query = (const float*)d_in[0];
    const float* key   = (const float*)d_in[1];
    const float* value = (const float*)d_in[2];
    const float* wq    = (const float*)d_in[3];
    const float* bq    = (const float*)d_in[4];
    const float* wk    = (const float*)d_in[5];
    const float* bk    = (const float*)d_in[6];
    const float* wv    = (const float*)d_in[7];
    const float* bv    = (const float*)d_in[8];
    const float* wo    = (const float*)d_in[9];
    const float* bo    = (const float*)d_in[10];
    float* out = (float*)d_out;

    cudaFuncSetAttribute(qkv_kernel,     cudaFuncAttributeMaxDynamicSharedMemorySize, GSMEM);
    cudaFuncSetAttribute(outproj_kernel, cudaFuncAttributeMaxDynamicSharedMemorySize, GSMEM);
    cudaFuncSetAttribute(attn_kernel,    cudaFuncAttributeMaxDynamicSharedMemorySize, ATTN_SMEM);

    dim3 blk256(256);
    conv_x_kernel<<<dim3(XEL / 2048, 3), blk256>>>(query, key, value);
    transw_kernel<<<dim3(24, 24, 4), blk256>>>(wq, wk, wv, wo);

    qkv_kernel<<<dim3(MTOT / 128, Dn / 128, 3), blk256, GSMEM>>>(bq, bk, bv);

    // #4: attention (profiled window)
    attn_kernel<<<dim3(Sn / 128, Hn, Bn), blk256, ATTN_SMEM>>>();

    outproj_kernel<<<dim3(MTOT / 128, Dn / 128), blk256, GSMEM>>>(bo, out);
}

// round 17
// speedup vs baseline: 1.1099x; 1.0316x over previous
#include <cuda_runtime.h>
#include <cuda_fp16.h>
#include <cstdint>

#define Bn   4
#define Sn   2048
#define Dn   768
#define Hn   12
#define HDn  64
#define MTOT (Bn * Sn)   // 8192
#define XEL  (MTOT * Dn) // 6291456
#define WEL  (Dn * Dn)   // 589824

// Scratch — static device globals (no allocation)
__device__ __half g_q[Bn * Hn * Sn * HDn];     // [B,H,S,d], pre-scaled by log2e/8
__device__ __half g_k[Bn * Hn * Sn * HDn];     // [B,H,S,d]
__device__ __half g_vT[Bn * Hn * HDn * Sn];    // [B,H,d,S]
__device__ __half g_ctx[Bn * Hn * Sn * HDn];   // [B,H,S,d]
__device__ __half g_xh[3][XEL];                // fp16 q/k/v inputs
__device__ __half g_wh[4][WEL];                // fp16 TRANSPOSED weights [n][k]

#define SWZ(off) ((off) ^ (((off) >> 3) & 0x70))

__device__ __forceinline__ void cp16s(unsigned sa, const void* g) {
    asm volatile("cp.async.cg.shared.global [%0], [%1], 16;\n" :: "r"(sa), "l"(g));
}
__device__ __forceinline__ void cp_commit() { asm volatile("cp.async.commit_group;\n"); }
template <int N> __device__ __forceinline__ void cp_wait() {
    asm volatile("cp.async.wait_group %0;\n" :: "n"(N));
}
__device__ __forceinline__ void ldsm4(unsigned* d, unsigned a) {
    asm volatile("ldmatrix.sync.aligned.m8n8.x4.shared.b16 {%0,%1,%2,%3}, [%4];"
                 : "=r"(d[0]), "=r"(d[1]), "=r"(d[2]), "=r"(d[3]) : "r"(a));
}
__device__ __forceinline__ void mma16(float* d, const unsigned* a, unsigned b0, unsigned b1) {
    asm volatile("mma.sync.aligned.m16n8k16.row.col.f32.f16.f16.f32 "
                 "{%0,%1,%2,%3}, {%4,%5,%6,%7}, {%8,%9}, {%0,%1,%2,%3};"
                 : "+f"(d[0]), "+f"(d[1]), "+f"(d[2]), "+f"(d[3])
                 : "r"(a[0]), "r"(a[1]), "r"(a[2]), "r"(a[3]), "r"(b0), "r"(b1));
}
// packed exp2: cvt two f32 to f16x2 (lo=a, hi=b), then ex2.approx.f16x2
__device__ __forceinline__ unsigned ex2h2(float a, float b) {
    unsigned c, r;
    asm("cvt.rn.f16x2.f32 %0, %1, %2;" : "=r"(c) : "f"(b), "f"(a));  // hi=b, lo=a
    asm("ex2.approx.f16x2 %0, %1;" : "=r"(r) : "r"(c));
    return r;
}

// ---------------------------------------------------------------------------
// fp16 conversion of activations (8 elems/thread)
// ---------------------------------------------------------------------------
__global__ void conv_x_kernel(const float* __restrict__ x0, const float* __restrict__ x1,
                              const float* __restrict__ x2) {
    const float* src = (blockIdx.y == 0) ? x0 : (blockIdx.y == 1) ? x1 : x2;
    __half* dst = g_xh[blockIdx.y];
    int i = (blockIdx.x * 256 + threadIdx.x) * 8;
    float4 a = *(const float4*)(src + i);
    float4 b = *(const float4*)(src + i + 4);
    __half2 h[4];
    h[0] = __floats2half2_rn(a.x, a.y);
    h[1] = __floats2half2_rn(a.z, a.w);
    h[2] = __floats2half2_rn(b.x, b.y);
    h[3] = __floats2half2_rn(b.z, b.w);
    *(uint4*)(dst + i) = *(uint4*)h;
}

// ---------------------------------------------------------------------------
// Transpose + fp16 weights: g_wh[z][n][k] = half(W_z[k][n])
// ---------------------------------------------------------------------------
__global__ void transw_kernel(const float* __restrict__ w0, const float* __restrict__ w1,
                              const float* __restrict__ w2, const float* __restrict__ w3) {
    const float* src = (blockIdx.z == 0) ? w0 : (blockIdx.z == 1) ? w1
                     : (blockIdx.z == 2) ? w2 : w3;
    __half* dst = g_wh[blockIdx.z];
    __shared__ float t[32][33];
    int kt = blockIdx.x * 32, nt = blockIdx.y * 32;
#pragma unroll
    for (int p = 0; p < 4; p++) {
        int e = threadIdx.x + 256 * p;
        int r = e >> 5, c = e & 31;
        t[r][c] = src[(size_t)(kt + r) * Dn + nt + c];
    }
    __syncthreads();
#pragma unroll
    for (int p = 0; p < 4; p++) {
        int e = threadIdx.x + 256 * p;
        int r = e >> 5, c = e & 31;
        dst[(size_t)(nt + r) * Dn + kt + c] = __float2half(t[c][r]);
    }
}

// ---------------------------------------------------------------------------
// Merged QKV projection — 3-stage cp.async pipeline, one sync per K-chunk.
// ---------------------------------------------------------------------------
#define GSMEM 99328

__global__ __launch_bounds__(256, 2)
void qkv_kernel(const float* __restrict__ bq, const float* __restrict__ bk,
                const float* __restrict__ bv)
{
    extern __shared__ char smc[];
    unsigned sb = (unsigned)__cvta_generic_to_shared(smc);
    unsigned ab = (sb + 1023u) & ~1023u;
    float* sst = (float*)(smc + (ab - sb));

    const int z = blockIdx.z;
    const __half* A  = g_xh[z];
    const __half* Wt = g_wh[z];
    const float* bias = (z == 0) ? bq : (z == 1) ? bk : bv;

    const int tid = threadIdx.x;
    const int w = tid >> 5, lane = tid & 31;
    const int wm = w & 1, wn = w >> 1;
    const int g = lane >> 2, tg = lane & 3;
    const int m0 = blockIdx.x * 128, n0 = blockIdx.y * 128;
    const int b_ = m0 >> 11, s0 = m0 & 2047;

    float acc[4][4][4];
#pragma unroll
    for (int mi = 0; mi < 4; mi++)
#pragma unroll
        for (int ni = 0; ni < 4; ni++)
#pragma unroll
            for (int e = 0; e < 4; e++) acc[mi][ni][e] = 0.0f;

    auto issue = [&](int c) {
        unsigned buf = (unsigned)(c % 3) * 32768u;
        int k0 = c * 64;
#pragma unroll
        for (int jj = 0; jj < 4; jj++) {
            int i = tid + 256 * jj;
            int r = i >> 3, c8 = i & 7;
            cp16s(ab + buf + SWZ(r * 128 + c8 * 16), A + (size_t)(m0 + r) * Dn + k0 + c8 * 8);
        }
#pragma unroll
        for (int jj = 0; jj < 4; jj++) {
            int i = tid + 256 * jj;
            int r = i >> 3, c8 = i & 7;
            cp16s(ab + buf + 16384u + SWZ(r * 128 + c8 * 16),
                  Wt + (size_t)(n0 + r) * Dn + k0 + c8 * 8);
        }
        cp_commit();
    };

    issue(0);
    issue(1);
    const int arow = lane & 15, ak = (lane >> 4) * 16;

    for (int c = 0; c < 12; c++) {
        if (c < 11) cp_wait<1>(); else cp_wait<0>();
        __syncthreads();
        if (c + 2 < 12) issue(c + 2);
        unsigned abase = ab + (unsigned)(c % 3) * 32768u;
        unsigned bbase = abase + 16384u;
#pragma unroll
        for (int s = 0; s < 4; s++) {
            unsigned ar[4][4], br[2][4];
#pragma unroll
            for (int mi = 0; mi < 4; mi++)
                ldsm4(ar[mi], abase + SWZ((wm * 64 + mi * 16 + arow) * 128 + s * 32 + ak));
#pragma unroll
            for (int nj = 0; nj < 2; nj++)
                ldsm4(br[nj], bbase + SWZ((wn * 32 + nj * 16 + arow) * 128 + s * 32 + ak));
#pragma unroll
            for (int mi = 0; mi < 4; mi++)
#pragma unroll
                for (int ni = 0; ni < 4; ni++)
                    mma16(acc[mi][ni], ar[mi], br[ni >> 1][ni & 1], br[ni >> 1][(ni & 1) + 2]);
        }
    }
    __syncthreads();

#pragma unroll
    for (int mi = 0; mi < 4; mi++)
#pragma unroll
        for (int ni = 0; ni < 4; ni++) {
            int row0 = wm * 64 + mi * 16 + g;
            int col = wn * 32 + ni * 8 + tg * 2;
            *(float2*)(sst + row0 * 132 + col) = make_float2(acc[mi][ni][0], acc[mi][ni][1]);
            *(float2*)(sst + (row0 + 8) * 132 + col) = make_float2(acc[mi][ni][2], acc[mi][ni][3]);
        }
    __syncthreads();

    if (z < 2) {
        __half* outh = (z == 0) ? g_q : g_k;
        float scale = (z == 0) ? (0.125f * 1.44269504f) : 1.0f;
        int col = tid & 127, rh = (tid >> 7) * 64;
        int nn = n0 + col, hh = nn >> 6, dd = nn & 63;
        float bvl = bias[nn];
        __half* op = outh + (((size_t)b_ * Hn + hh) * Sn + s0) * HDn + dd;
        for (int r = rh; r < rh + 64; r++)
            op[(size_t)r * HDn] = __float2half(scale * (sst[r * 132 + col] + bvl));
    } else {
        int r = tid & 127, ch = (tid >> 7) * 64;
        for (int c = ch; c < ch + 64; c++) {
            int nn = n0 + c, hh = nn >> 6, dd = nn & 63;
            g_vT[(((size_t)b_ * Hn + hh) * HDn + dd) * Sn + s0 + r] =
                __float2half(sst[r * 132 + c] + bias[nn]);
        }
    }
}

// ---------------------------------------------------------------------------
// Output projection — same 3-stage, 1-sync pipeline.
// ---------------------------------------------------------------------------
__global__ __launch_bounds__(256, 2)
void outproj_kernel(const float* __restrict__ bias, float* __restrict__ out)
{
    extern __shared__ char smc[];
    unsigned sb = (unsigned)__cvta_generic_to_shared(smc);
    unsigned ab = (sb + 1023u) & ~1023u;
    float* sst = (float*)(smc + (ab - sb));

    const __half* Wt = g_wh[3];
    const int tid = threadIdx.x;
    const int w = tid >> 5, lane = tid & 31;
    const int wm = w & 1, wn = w >> 1;
    const int g = lane >> 2, tg = lane & 3;
    const int m0 = blockIdx.x * 128, n0 = blockIdx.y * 128;
    const int b_ = m0 >> 11, s0 = m0 & 2047;

    float acc[4][4][4];
#pragma unroll
    for (int mi = 0; mi < 4; mi++)
#pragma unroll
        for (int ni = 0; ni < 4; ni++)
#pragma unroll
            for (int e = 0; e < 4; e++) acc[mi][ni][e] = 0.0f;

    auto issue = [&](int c) {
        unsigned buf = (unsigned)(c % 3) * 32768u;
#pragma unroll
        for (int jj = 0; jj < 4; jj++) {
            int i = tid + 256 * jj;
            int r = i >> 3, c8 = i & 7;
            cp16s(ab + buf + SWZ(r * 128 + c8 * 16),
                  g_ctx + (((size_t)b_ * Hn + c) * Sn + s0 + r) * HDn + c8 * 8);
        }
#pragma unroll
        for (int jj = 0; jj < 4; jj++) {
            int i = tid + 256 * jj;
            int r = i >> 3, c8 = i & 7;
            cp16s(ab + buf + 16384u + SWZ(r * 128 + c8 * 16),
                  Wt + (size_t)(n0 + r) * Dn + c * 64 + c8 * 8);
        }
        cp_commit();
    };

    issue(0);
    issue(1);
    const int arow = lane & 15, ak = (lane >> 4) * 16;

    for (int c = 0; c < 12; c++) {
        if (c < 11) cp_wait<1>(); else cp_wait<0>();
        __syncthreads();
        if (c + 2 < 12) issue(c + 2);
        unsigned abase = ab + (unsigned)(c % 3) * 32768u;
        unsigned bbase = abase + 16384u;
#pragma unroll
        for (int s = 0; s < 4; s++) {
            unsigned ar[4][4], br[2][4];
#pragma unroll
            for (int mi = 0; mi < 4; mi++)
                ldsm4(ar[mi], abase + SWZ((wm * 64 + mi * 16 + arow) * 128 + s * 32 + ak));
#pragma unroll
            for (int nj = 0; nj < 2; nj++)
                ldsm4(br[nj], bbase + SWZ((wn * 32 + nj * 16 + arow) * 128 + s * 32 + ak));
#pragma unroll
            for (int mi = 0; mi < 4; mi++)
#pragma unroll
                for (int ni = 0; ni < 4; ni++)
                    mma16(acc[mi][ni], ar[mi], br[ni >> 1][ni & 1], br[ni >> 1][(ni & 1) + 2]);
        }
    }
    __syncthreads();

#pragma unroll
    for (int mi = 0; mi < 4; mi++)
#pragma unroll
        for (int ni = 0; ni < 4; ni++) {
            int row0 = wm * 64 + mi * 16 + g;
            int col = wn * 32 + ni * 8 + tg * 2;
            *(float2*)(sst + row0 * 132 + col) = make_float2(acc[mi][ni][0], acc[mi][ni][1]);
            *(float2*)(sst + (row0 + 8) * 132 + col) = make_float2(acc[mi][ni][2], acc[mi][ni][3]);
        }
    __syncthreads();

    int col = tid & 127, rh = (tid >> 7) * 64;
    float bvl = bias[n0 + col];
    float* op = out + (size_t)m0 * Dn + n0 + col;
    for (int r = rh; r < rh + 64; r++)
        op[(size_t)r * Dn] = sst[r * 132 + col] + bvl;
}

// ---------------------------------------------------------------------------
// fp16 fused attention v3 — R15 structure (register P, 1 sync/tile) with:
//  * QK^T processes n-groups in PAIRS (4 independent HMMA chains, hides latency)
//  * ex2 via cvt.f16x2 + ex2.approx.f16x2 (half the MUFU, pack fused)
// smem: 1KB pad + QS 16KB | KS 2x16KB | VS 2x16KB | SONE 2KB | lrow 512B
// ---------------------------------------------------------------------------
#define ATTN_SMEM 85504

__global__ __launch_bounds__(256, 2)
void attn_kernel()
{
    extern __shared__ char smc[];
    unsigned sb = (unsigned)__cvta_generic_to_shared(smc);
    unsigned ab = (sb + 1023u) & ~1023u;
    char* abp = smc + (ab - sb);

    const unsigned QS = ab;
    const unsigned KS = ab + 16384u;        // 2 x 16KB
    const unsigned VS = ab + 49152u;        // 2 x 16KB (each: 2 panels [64][64])
    const unsigned SONE = ab + 81920u;      // 2KB ones-block
    float* lrow = (float*)(abp + 83968);    // [128]

    const int tid = threadIdx.x;
    const int w = tid >> 5, lane = tid & 31;
    const int g = lane >> 2, tg = lane & 3;
    const int b = blockIdx.z, h = blockIdx.y, q0 = blockIdx.x * 128;
    const int wq = w * 16;                  // this warp's 16 q rows

    const __half* Qg  = g_q  + (((size_t)b * Hn + h) * Sn + q0) * HDn;
    const __half* Kg  = g_k  + (((size_t)b * Hn + h) * Sn) * HDn;
    const __half* VTg = g_vT + (((size_t)b * Hn + h) * HDn) * Sn;

    auto issueK = [&](int t) {
        unsigned kb = KS + (unsigned)(t & 1) * 16384u;
#pragma unroll
        for (int jj = 0; jj < 4; jj++) {
            int i = tid + 256 * jj;
            int r = i >> 3, c8 = i & 7;
            cp16s(kb + SWZ(r * 128 + c8 * 16), Kg + (size_t)(t * 128 + r) * HDn + c8 * 8);
        }
        cp_commit();
    };
    auto issueV = [&](int t) {
        unsigned vb = VS + (unsigned)(t & 1) * 16384u;
#pragma unroll
        for (int jj = 0; jj < 4; jj++) {
            int i = tid + 256 * jj;
            int r = i >> 4, c16 = i & 15;
            cp16s(vb + (unsigned)(c16 >> 3) * 8192u + SWZ(r * 128 + (c16 & 7) * 16),
                  VTg + (size_t)r * Sn + t * 128 + c16 * 8);
        }
        cp_commit();
    };

    // Prologue
#pragma unroll
    for (int jj = 0; jj < 4; jj++) {
        int i = tid + 256 * jj;
        int r = i >> 3, c8 = i & 7;
        cp16s(QS + SWZ(r * 128 + c8 * 16), Qg + (size_t)r * HDn + c8 * 8);
    }
    issueK(0);
    issueV(0);

#pragma unroll
    for (int jj = 0; jj < 2; jj++) {
        int idx = tid + 256 * jj;
        int row = idx >> 5, wd = idx & 31;
        int chunk = wd >> 2, ww = wd & 3;
        unsigned val = (row == 0) ? 0x3C003C00u : 0u;
        asm volatile("st.shared.u32 [%0], %1;"
                     :: "r"(SONE + SWZ(row * 128 + chunk * 16) + ww * 4), "r"(val));
    }

    float oacc[8][4];
#pragma unroll
    for (int dn = 0; dn < 8; dn++)
#pragma unroll
        for (int e = 0; e < 4; e++) oacc[dn][e] = 0.0f;
    float osum[4] = {0.f, 0.f, 0.f, 0.f};

    cp_wait<0>();
    __syncthreads();

    const int arow = lane & 15, ak = (lane >> 4) * 16;

    unsigned sfr[4];
    ldsm4(sfr, SONE + SWZ(arow * 128 + ak));
    const unsigned so0 = sfr[0], so1 = sfr[2];

    unsigned qfr[4][4];
#pragma unroll
    for (int s = 0; s < 4; s++)
        ldsm4(qfr[s], QS + SWZ((wq + arow) * 128 + s * 32 + ak));

    for (int kt = 0; kt < 16; kt++) {
        if (kt) { cp_wait<0>(); __syncthreads(); }
        if (kt + 1 < 16) { issueK(kt + 1); issueV(kt + 1); }

        unsigned kb = KS + (unsigned)(kt & 1) * 16384u;
        unsigned vb = VS + (unsigned)(kt & 1) * 16384u;

        // ---- QK^T + exp, n-groups in pairs (4 independent mma chains) ----
        unsigned pk[16][2];
#pragma unroll
        for (int np2 = 0; np2 < 4; np2++) {
            float sacc[4][4];
#pragma unroll
            for (int j = 0; j < 4; j++)
#pragma unroll
                for (int e = 0; e < 4; e++) sacc[j][e] = 0.0f;
#pragma unroll
            for (int s = 0; s < 4; s++) {
                unsigned br0[4], br1[4];
                ldsm4(br0, kb + SWZ(((np2 * 2) * 16 + arow) * 128 + s * 32 + ak));
                ldsm4(br1, kb + SWZ(((np2 * 2 + 1) * 16 + arow) * 128 + s * 32 + ak));
                mma16(sacc[0], qfr[s], br0[0], br0[2]);
                mma16(sacc[1], qfr[s], br0[1], br0[3]);
                mma16(sacc[2], qfr[s], br1[0], br1[2]);
                mma16(sacc[3], qfr[s], br1[1], br1[3]);
            }
#pragma unroll
            for (int j = 0; j < 4; j++) {
                pk[np2 * 4 + j][0] = ex2h2(sacc[j][0], sacc[j][1]);
                pk[np2 * 4 + j][1] = ex2h2(sacc[j][2], sacc[j][3]);
            }
        }

        // ---- O += P @ V ; osum += P @ ones (A from registers) ----
#pragma unroll
        for (int c = 0; c < 8; c++) {
            unsigned a[4] = { pk[2 * c][0], pk[2 * c][1],
                              pk[2 * c + 1][0], pk[2 * c + 1][1] };
            unsigned vp = vb + (unsigned)(c >> 2) * 8192u;
            int ko = (c & 3) * 32;
#pragma unroll
            for (int dp = 0; dp < 4; dp++) {
                unsigned br[4];
                ldsm4(br, vp + SWZ((dp * 16 + arow) * 128 + ko + ak));
                mma16(oacc[dp * 2],     a, br[0], br[2]);
                mma16(oacc[dp * 2 + 1], a, br[1], br[3]);
            }
            mma16(osum, a, so0, so1);
        }
    }

    // ---- epilogue ----
    __syncthreads();
    if (tg == 0) {
        lrow[wq + g]     = osum[0];
        lrow[wq + 8 + g] = osum[2];
    }
    float* sst = (float*)abp;        // [128][68] f32 over dead QS+KS0
#pragma unroll
    for (int dn = 0; dn < 8; dn++) {
        int row0 = wq + g;
        int col = dn * 8 + tg * 2;
        *(float2*)(sst + row0 * 68 + col) = make_float2(oacc[dn][0], oacc[dn][1]);
        *(float2*)(sst + (row0 + 8) * 68 + col) = make_float2(oacc[dn][2], oacc[dn][3]);
    }
    __syncthreads();

    __half* Cg = g_ctx + (((size_t)b * Hn + h) * Sn + q0) * HDn;
    for (int idx = tid; idx < 128 * 32; idx += 256) {
        int r = idx >> 5, c2 = (idx & 31) * 2;
        float inv = 1.0f / lrow[r];
        __half2 hv = __floats2half2_rn(sst[r * 68 + c2] * inv, sst[r * 68 + c2 + 1] * inv);
        *(unsigned*)(Cg + (size_t)r * HDn + c2) = *(unsigned*)&hv;
    }
}

// ---------------------------------------------------------------------------
extern "C" void kernel_launch(void* const* d_in, const int* in_sizes, int n_in,
                              void* d_out, int out_size)
{
    const float* query = (const float*)d_in[0];
    const float* key   = (const float*)d_in[1];
    const float* value = (const float*)d_in[2];
    const float* wq    = (const float*)d_in[3];
    const float* bq    = (const float*)d_in[4];
    const float* wk    = (const float*)d_in[5];
    const float* bk    = (const float*)d_in[6];
    const float* wv    = (const float*)d_in[7];
    const float* bv    = (const float*)d_in[8];
    const float* wo    = (const float*)d_in[9];
    const float* bo    = (const float*)d_in[10];
    float* out = (float*)d_out;

    cudaFuncSetAttribute(qkv_kernel,     cudaFuncAttributeMaxDynamicSharedMemorySize, GSMEM);
    cudaFuncSetAttribute(outproj_kernel, cudaFuncAttributeMaxDynamicSharedMemorySize, GSMEM);
    cudaFuncSetAttribute(attn_kernel,    cudaFuncAttributeMaxDynamicSharedMemorySize, ATTN_SMEM);

    dim3 blk256(256);
    conv_x_kernel<<<dim3(XEL / 2048, 3), blk256>>>(query, key, value);
    transw_kernel<<<dim3(24, 24, 4), blk256>>>(wq, wk, wv, wo);

    qkv_kernel<<<dim3(MTOT / 128, Dn / 128, 3), blk256, GSMEM>>>(bq, bk, bv);

    // #4: attention (profiled window)
    attn_kernel<<<dim3(Sn / 128, Hn, Bn), blk256, ATTN_SMEM>>>();

    outproj_kernel<<<dim3(MTOT / 128, Dn / 128), blk256, GSMEM>>>(bo, out);
}